// round 15
// baseline (speedup 1.0000x reference)
#include <cuda_runtime.h>
#include <cstdint>

#define GRID_N   7
#define NB       2
#define NC       20
#define IS       8
#define DCH      30
#define L_BOX    5.0f
#define L_NEG    0.5f

#define TPB      128
#define WARPS    (TPB / 32)
#define NBLOCKS  444            // 148 SMs x 3 blocks (61KB smem each) = one wave
#define MAX_BLOCKS 1024

// per tile: 32 cells x 30 floats = 960 floats = 240 float4 per tensor
#define T4       240

__device__ double g_partials[MAX_BLOCKS];
__device__ unsigned int g_count = 0;

__device__ __forceinline__ void cp_async16(uint32_t dst, const void* src) {
    asm volatile("cp.async.cg.shared.global [%0], [%1], 16;\n" :: "r"(dst), "l"(src));
}
__device__ __forceinline__ void cp_commit() {
    asm volatile("cp.async.commit_group;\n" ::: "memory");
}
__device__ __forceinline__ void cp_wait1() {
    asm volatile("cp.async.wait_group 1;\n" ::: "memory");
}
__device__ __forceinline__ void cp_wait0() {
    asm volatile("cp.async.wait_group 0;\n" ::: "memory");
}

__device__ __forceinline__ float bce_t(float x) {           // 1 + exp(-|x|)
    return 1.0f + __expf(-fabsf(x));
}
__device__ __forceinline__ float sigm(float x) {
    return __fdividef(1.0f, 1.0f + __expf(-x));
}
// box loss with pre-sqrt'd wh terms
__device__ __forceinline__ float bl(float px, float py, float spw, float sph,
                                    float gx, float gy, float sgw, float sgh) {
    float dx = px - gx, dy = py - gy, dw = spw - sgw, dh = sph - sgh;
    return dx * dx + dy * dy + dw * dw + dh * dh;
}

// positive-cell loss (box + conf-linear + cls-linear); *prod_out carries the
// combined bce_t product whose single log the caller applies.
// NOTE: cell col/row dropped — IoU is invariant to the common +cr/GRID shift.
__device__ __forceinline__ float pos_cell(const float2* __restrict__ pc2,
                                          const float2* __restrict__ gc2,
                                          float2 pconf, float bt8, float bt9,
                                          float* __restrict__ prod_out) {
    float2 a0 = pc2[0], a1 = pc2[1], a2 = pc2[2], a3 = pc2[3];
    float2 b0 = gc2[0], b1 = gc2[1], b2 = gc2[2], b3 = gc2[3];

    float sx[NB]  = { sigm(a0.x), sigm(a2.x) };
    float sy[NB]  = { sigm(a0.y), sigm(a2.y) };
    float pw[NB]  = { a1.x, a3.x };
    float ph[NB]  = { a1.y, a3.y };
    float gx[NB]  = { b0.x, b2.x };
    float gy[NB]  = { b0.y, b2.y };
    float gw[NB]  = { b1.x, b3.x };
    float gh[NB]  = { b1.y, b3.y };

    // sqrts computed once
    float spw[NB] = { sqrtf(fabsf(pw[0])), sqrtf(fabsf(pw[1])) };
    float sph[NB] = { sqrtf(fabsf(ph[0])), sqrtf(fabsf(ph[1])) };
    float sgw[NB] = { sqrtf(gw[0]), sqrtf(gw[1]) };
    float sgh[NB] = { sqrtf(gh[0]), sqrtf(gh[1]) };

    // ltrb (no cell shift) — keep the exact (rb-lt) area form of the reference
    float pl[NB][4], gl[NB][4];
    #pragma unroll
    for (int b = 0; b < NB; b++) {
        float cx = sx[b] * (1.0f / GRID_N);
        float cy = sy[b] * (1.0f / GRID_N);
        pl[b][0] = cx - pw[b] * 0.5f; pl[b][1] = cy - ph[b] * 0.5f;
        pl[b][2] = cx + pw[b] * 0.5f; pl[b][3] = cy + ph[b] * 0.5f;
        float gcx = gx[b] * (1.0f / GRID_N);
        float gcy = gy[b] * (1.0f / GRID_N);
        gl[b][0] = gcx - gw[b] * 0.5f; gl[b][1] = gcy - gh[b] * 0.5f;
        gl[b][2] = gcx + gw[b] * 0.5f; gl[b][3] = gcy + gh[b] * 0.5f;
    }

    float iou[NB][NB];
    #pragma unroll
    for (int pi = 0; pi < NB; pi++) {
        float aa = (pl[pi][2] - pl[pi][0]) * (pl[pi][3] - pl[pi][1]);
        #pragma unroll
        for (int gi = 0; gi < NB; gi++) {
            float ltx = fmaxf(pl[pi][0], gl[gi][0]);
            float lty = fmaxf(pl[pi][1], gl[gi][1]);
            float rbx = fminf(pl[pi][2], gl[gi][2]);
            float rby = fminf(pl[pi][3], gl[gi][3]);
            float wx = fmaxf(rbx - ltx, 0.0f);
            float wy = fmaxf(rby - lty, 0.0f);
            float inter = wx * wy;
            float ab = (gl[gi][2] - gl[gi][0]) * (gl[gi][3] - gl[gi][1]);
            iou[pi][gi] = __fdividef(inter, aa + ab - inter + 1e-7f);
        }
    }

    int ind0 = (iou[1][0] > iou[0][0]) ? 1 : 0;
    int ind1 = (iou[1][1] > iou[0][1]) ? 1 : 0;

    bool same_g = (gx[0] == gx[1]) && (gy[0] == gy[1]) &&
                  (gw[0] == gw[1]) && (gh[0] == gh[1]);
    bool same_ind = (ind0 == ind1);

    float box_cell;
    if (same_g) {
        box_cell = bl(sx[ind0], sy[ind0], spw[ind0], sph[ind0],
                      gx[0], gy[0], sgw[0], sgh[0]);
    } else if (same_ind) {
        box_cell = bl(sx[0], sy[0], spw[0], sph[0], gx[0], gy[0], sgw[0], sgh[0])
                 + bl(sx[1], sy[1], spw[1], sph[1], gx[1], gy[1], sgw[1], sgh[1]);
    } else {
        box_cell = bl(sx[ind0], sy[ind0], spw[ind0], sph[ind0],
                      gx[0], gy[0], sgw[0], sgh[0])
                 + bl(sx[ind1], sy[ind1], spw[ind1], sph[ind1],
                      gx[1], gy[1], sgw[1], sgh[1]);
    }

    float conf_lin, conf_prod;
    if (same_g) {
        float x = ind1 ? pconf.y : pconf.x;
        conf_lin = fmaxf(x, 0.f) - x;
        conf_prod = ind1 ? bt9 : bt8;
    } else {
        conf_lin = fmaxf(pconf.x, 0.f) - pconf.x + fmaxf(pconf.y, 0.f) - pconf.y;
        conf_prod = bt8 * bt9;
    }

    // cls: two independent chains, prod seeded with conf product
    const float2* pcl2 = pc2 + 5;
    const float2* gcl2 = gc2 + 5;
    float lin0 = 0.0f, lin1 = 0.0f, prod0 = conf_prod, prod1 = 1.0f;
    #pragma unroll
    for (int i = 0; i < 5; i++) {
        float2 a = pcl2[i];
        float2 b = gcl2[i];
        lin0  += fmaxf(a.x, 0.f) - a.x * b.x + fmaxf(a.y, 0.f) - a.y * b.y;
        prod0 *= bce_t(a.x) * bce_t(a.y);
        float2 c = pcl2[i + 5];
        float2 d = gcl2[i + 5];
        lin1  += fmaxf(c.x, 0.f) - c.x * d.x + fmaxf(c.y, 0.f) - c.y * d.y;
        prod1 *= bce_t(c.x) * bce_t(c.y);
    }
    *prod_out = prod0 * prod1;   // <= 2^22: safe in fp32
    return L_BOX * box_cell + conf_lin + lin0 + lin1;
}

// stage one tile (p then g), trimmed: 7 full warp-steps + half-step
__device__ __forceinline__ void stage_tile(uint32_t dst, const float* __restrict__ p,
                                           const float* __restrict__ g,
                                           int tile, int lane) {
    const float4* psrc = reinterpret_cast<const float4*>(p + (size_t)tile * 32 * DCH) + lane;
    const float4* gsrc = reinterpret_cast<const float4*>(g + (size_t)tile * 32 * DCH) + lane;
    uint32_t pd = dst + lane * 16;
    uint32_t gd = dst + T4 * 16 + lane * 16;
    #pragma unroll
    for (int k = 0; k < 7; k++) {
        cp_async16(pd + k * 512, psrc + 32 * k);
        cp_async16(gd + k * 512, gsrc + 32 * k);
    }
    if (lane < 16) {
        cp_async16(pd + 7 * 512, psrc + 224);
        cp_async16(gd + 7 * 512, gsrc + 224);
    }
    cp_commit();
}

__global__ void __launch_bounds__(TPB)
yolo_loss_kernel(const float* __restrict__ p, const float* __restrict__ g,
                 int ncells, float* __restrict__ out, float inv_nb) {
    // per-warp double buffer: [stage][p(240f4) | g(240f4)]
    __shared__ float4 sbuf[WARPS][2][2 * T4];    // 4 * 2 * 480 * 16 = 61440 B

    const int tid  = threadIdx.x;
    const int lane = tid & 31;
    const int wid  = tid >> 5;
    const int warpGlobal = blockIdx.x * WARPS + wid;
    const int nwarps = gridDim.x * WARPS;
    const int ntiles = ncells >> 5;

    uint32_t bufA = (uint32_t)__cvta_generic_to_shared(&sbuf[wid][0][0]);
    uint32_t bufB = (uint32_t)__cvta_generic_to_shared(&sbuf[wid][1][0]);

    float acc = 0.0f;

    int t = warpGlobal;
    if (t < ntiles) stage_tile(bufA, p, g, t, lane);

    int cur = 0;
    for (; t < ntiles; t += nwarps) {
        int tn = t + nwarps;
        bool pf = (tn < ntiles);
        if (pf) stage_tile(cur ? bufA : bufB, p, g, tn, lane);

        if (pf) cp_wait1(); else cp_wait0();
        __syncwarp();

        const float* base = reinterpret_cast<const float*>(&sbuf[wid][cur][0]);
        const float2* pc2 = reinterpret_cast<const float2*>(base + lane * DCH);
        const float2* gc2 = reinterpret_cast<const float2*>(base + 4 * T4 + lane * DCH);

        float2 pconf = pc2[4];
        float  conf_g = gc2[4].x;
        float bt8 = bce_t(pconf.x);
        float bt9 = bce_t(pconf.y);

        float lin, prod;
        if (conf_g > 0.0f) {
            lin = pos_cell(pc2, gc2, pconf, bt8, bt9, &prod);
        } else {
            lin  = L_NEG * (fmaxf(pconf.x, 0.f) + fmaxf(pconf.y, 0.f));
            prod = sqrtf(bt8 * bt9);     // (bt8*bt9)^L_NEG, L_NEG = 0.5
        }
        acc += lin + __logf(prod);       // single log per lane, post-reconvergence

        __syncwarp();
        cur ^= 1;
    }

    // tail cells (ncells % 32): block 0 warp 0, direct gmem
    if (blockIdx.x == 0 && wid == 0) {
        int idx = ntiles * 32 + lane;
        if (idx < ncells) {
            const float2* pc2 = reinterpret_cast<const float2*>(p + (size_t)idx * DCH);
            const float2* gc2 = reinterpret_cast<const float2*>(g + (size_t)idx * DCH);
            float2 pconf = pc2[4];
            float conf_g = gc2[4].x;
            float bt8 = bce_t(pconf.x), bt9 = bce_t(pconf.y);
            float lin, prod;
            if (conf_g > 0.0f) {
                lin = pos_cell(pc2, gc2, pconf, bt8, bt9, &prod);
            } else {
                lin  = L_NEG * (fmaxf(pconf.x, 0.f) + fmaxf(pconf.y, 0.f));
                prod = sqrtf(bt8 * bt9);
            }
            acc += lin + __logf(prod);
        }
    }

    // ---- deterministic block reduction ----
    #pragma unroll
    for (int o = 16; o > 0; o >>= 1)
        acc += __shfl_down_sync(0xffffffffu, acc, o);

    __shared__ float warp_sums[WARPS];
    if (lane == 0) warp_sums[wid] = acc;
    __syncthreads();

    if (tid == 0) {
        float v = 0.0f;
        #pragma unroll
        for (int w = 0; w < WARPS; w++) v += warp_sums[w];
        g_partials[blockIdx.x] = (double)v;
    }

    // ---- last-block finalization (deterministic fixed-order sum) ----
    __shared__ bool isLast;
    if (tid == 0) {
        __threadfence();
        unsigned int v = atomicAdd(&g_count, 1u);
        isLast = (v == gridDim.x - 1);
    }
    __syncthreads();

    if (isLast) {
        __shared__ double sh[TPB];
        double s = 0.0;
        for (int i = tid; i < (int)gridDim.x; i += TPB)
            s += g_partials[i];
        sh[tid] = s;
        __syncthreads();
        #pragma unroll
        for (int strideR = TPB / 2; strideR > 0; strideR >>= 1) {
            if (tid < strideR) sh[tid] += sh[tid + strideR];
            __syncthreads();
        }
        if (tid == 0) {
            out[0] = (float)(sh[0] * (double)inv_nb);
            g_count = 0;   // reset for next graph replay
        }
    }
}

extern "C" void kernel_launch(void* const* d_in, const int* in_sizes, int n_in,
                              void* d_out, int out_size) {
    const float* p = (const float*)d_in[0];
    const float* g = (const float*)d_in[1];
    float* out = (float*)d_out;

    int ncells = in_sizes[0] / DCH;                 // B * 49
    int batch  = ncells / (GRID_N * GRID_N);        // B
    int ntiles = ncells >> 5;

    int nblocks = NBLOCKS;
    int needed = (ntiles + WARPS - 1) / WARPS;
    if (needed < 1) needed = 1;
    if (nblocks > needed) nblocks = needed;
    if (nblocks > MAX_BLOCKS) nblocks = MAX_BLOCKS;

    yolo_loss_kernel<<<nblocks, TPB>>>(p, g, ncells, out, 1.0f / (float)batch);
}